// round 7
// baseline (speedup 1.0000x reference)
#include <cuda_runtime.h>
#include <math.h>

// ---------------- problem constants ----------------
#define NB 16
#define NS 25
#define NQ 15
#define NWAY 5
#define NIMG 640            // 400 support + 240 query
#define HL 32
#define DEMB 1600           // 5*5*64
#define GATES 128           // 4*HL

// ---------------- scratch (device globals; no allocations allowed) ----------------
__device__ float g_buf1[640 * 42 * 42 * 64];   // after layer1 pool
__device__ float g_buf2[640 * 21 * 21 * 64];   // after layer2 pool
__device__ float g_buf3[640 * 10 * 10 * 64];   // after layer3 pool
__device__ float g_emb [640 * DEMB];           // embeddings (5*5*64)
__device__ float g_xwkf[640 * GATES];          // emb @ Wk_fwd + b_fwd
__device__ float g_xwkb[640 * GATES];          // emb @ Wk_bwd + b_bwd
__device__ float g_sf[NS * NB * HL];           // support fwd hiddens [s][b][32]
__device__ float g_sb[NS * NB * HL];           // support bwd hiddens [s][b][32]
__device__ float g_qf[NQ * NB * HL];           // query fwd hiddens   [q][b][32]
__device__ float g_qb[NQ * NB * HL];           // query bwd hiddens   [q][b][32]

// duplicated weights for f32x2: [(ky*3+kx)][cin][32] float4 = (w[oc],w[oc],w[oc+32],w[oc+32])
// layer offsets (float4 units): L1 @0 (9*3*32=864), L2 @864, L3 @19296, L4 @37728
__device__ float4 g_wdup[9 * 3 * 32 + 3 * 9 * 64 * 32];

// ---------------- f32x2 helpers ----------------
__device__ __forceinline__ unsigned long long pk2(float lo, float hi) {
    unsigned long long r;
    asm("mov.b64 %0, {%1,%2};" : "=l"(r) : "f"(lo), "f"(hi));
    return r;
}
__device__ __forceinline__ void upk2(unsigned long long v, float& lo, float& hi) {
    asm("mov.b64 {%0,%1}, %2;" : "=f"(lo), "=f"(hi) : "l"(v));
}
__device__ __forceinline__ void fma2(unsigned long long& d,
                                     unsigned long long a, unsigned long long b) {
    asm("fma.rn.f32x2 %0, %1, %2, %3;" : "=l"(d) : "l"(a), "l"(b), "l"(d));
}

// ---------------- weight duplication prep ----------------
// src: [3][3][CIN][64]  ->  dst: [9][CIN][32] float4 (w_oc, w_oc, w_oc32, w_oc32)
__global__ void prep_w(const float* __restrict__ wt, float4* __restrict__ dst, int CIN)
{
    int i = blockIdx.x * 256 + threadIdx.x;
    int n = 9 * CIN * 32;
    if (i >= n) return;
    int oc   = i & 31;
    int rest = i >> 5;
    int cin  = rest % CIN;
    int k    = rest / CIN;
    float a = wt[(k * CIN + cin) * 64 + oc];
    float b = wt[(k * CIN + cin) * 64 + oc + 32];
    dst[i] = make_float4(a, a, b, b);
}

// ---------------- fused conv3x3(SAME) + BN + ReLU + maxpool2x2 (f32x2 math) ------
// 256 threads = 32 oc-lanes x 8 spatial tiles (one warp per spatial tile).
// Thread: 2 out-channels (oc, oc+32), 2 conv rows x 4 conv cols -> 1 pooled row
// x 2 pooled cols. Accumulators are f32x2 pairs over the column dimension.
template <int CIN, int H, int PH, int TTR, int TTC, bool FIRST>
__global__ void __launch_bounds__(256, 2)
conv_bn_relu_pool(const float* __restrict__ in,
                  const float* __restrict__ in_sup,
                  const float* __restrict__ in_qry,
                  const ulonglong2* __restrict__ wdup,  // [9][CIN][32] as (u64,u64)
                  const float* __restrict__ cb,
                  const float* __restrict__ gm,
                  const float* __restrict__ bt,
                  const float* __restrict__ mn,
                  const float* __restrict__ vr,
                  float* __restrict__ out)              // [N][PH][PH][64]
{
    constexpr int W    = H;
    constexpr int PW   = PH;
    constexpr int ROWS = 2 * TTR + 2;
    constexpr int COLS = 4 * TTC + 2;
    constexpr int STRIDE = (COLS + 3) & ~3;

    __shared__ __align__(16) float sIn[CIN * ROWS * STRIDE];

    const int tid = threadIdx.x;
    const int oc  = tid & 31;
    const int tt  = tid >> 5;
    const int a   = tt / TTC;
    const int tcc = tt % TTC;

    const int img = blockIdx.z;
    const int pr0 = blockIdx.y * TTR;
    const int pc0 = blockIdx.x * (2 * TTC);
    const int ir0 = 2 * pr0 - 1;
    const int ic0 = 2 * pc0 - 1;

    const float* base;
    if (FIRST) {
        base = (img < 400) ? (in_sup + (size_t)img * H * W * CIN)
                           : (in_qry + (size_t)(img - 400) * H * W * CIN);
    } else {
        base = in + (size_t)img * H * W * CIN;
    }

    constexpr int NELEM = CIN * ROWS * COLS;
    for (int e = tid; e < NELEM; e += 256) {
        int cin = e % CIN;
        int rc  = e / CIN;
        int r = rc / COLS, c = rc % COLS;
        int gr = ir0 + r, gc = ic0 + c;
        float v = 0.f;
        if (gr >= 0 && gr < H && gc >= 0 && gc < W)
            v = __ldg(base + ((size_t)gr * W + gc) * CIN + cin);
        sIn[(cin * ROWS + r) * STRIDE + c] = v;
    }
    __syncthreads();

    // acc2[half][row][pair]; pair 0 = cols(0,1), pair 1 = cols(2,3)
    unsigned long long acc2[2][2][2];
#pragma unroll
    for (int h = 0; h < 2; h++)
#pragma unroll
        for (int r = 0; r < 2; r++)
#pragma unroll
            for (int j = 0; j < 2; j++) acc2[h][r][j] = 0ull;

    const int sbase = 2 * a * STRIDE + 4 * tcc;
    const ulonglong2* wq0 = wdup + oc;    // + (k*CIN + cin)*32

    for (int cin = 0; cin < CIN; cin++) {
        // load 4 rows x 6 cols (vector broadcast), build the 5 shifted pairs/row
        unsigned long long X[4][5];
        const float* sp = &sIn[cin * ROWS * STRIDE + sbase];
#pragma unroll
        for (int rr = 0; rr < 4; rr++) {
            float4 v4 = *reinterpret_cast<const float4*>(sp + rr * STRIDE);
            float2 v2 = *reinterpret_cast<const float2*>(sp + rr * STRIDE + 4);
            X[rr][0] = pk2(v4.x, v4.y);
            X[rr][1] = pk2(v4.y, v4.z);
            X[rr][2] = pk2(v4.z, v4.w);
            X[rr][3] = pk2(v4.w, v2.x);
            X[rr][4] = pk2(v2.x, v2.y);
        }

        const ulonglong2* wq = wq0 + (size_t)cin * 32;
#pragma unroll
        for (int ky = 0; ky < 3; ky++)
#pragma unroll
            for (int kx = 0; kx < 3; kx++) {
                ulonglong2 wv = wq[(size_t)(ky * 3 + kx) * CIN * 32];
#pragma unroll
                for (int r = 0; r < 2; r++)
#pragma unroll
                    for (int j = 0; j < 2; j++) {
                        fma2(acc2[0][r][j], X[r + ky][kx + 2 * j], wv.x);
                        fma2(acc2[1][r][j], X[r + ky][kx + 2 * j], wv.y);
                    }
            }
    }

    // BN fold + ReLU + 2x2 maxpool + store (both oc halves)
    const int pr = pr0 + a;
#pragma unroll
    for (int h = 0; h < 2; h++) {
        const int och = oc + 32 * h;
        const float s = __ldg(gm + och) * rsqrtf(__ldg(vr + och) + 1e-3f);
        const float t = (__ldg(cb + och) - __ldg(mn + och)) * s + __ldg(bt + och);

        float v[2][4];
#pragma unroll
        for (int r = 0; r < 2; r++)
#pragma unroll
            for (int j = 0; j < 2; j++)
                upk2(acc2[h][r][j], v[r][2 * j], v[r][2 * j + 1]);

#pragma unroll
        for (int r = 0; r < 2; r++)
#pragma unroll
            for (int c = 0; c < 4; c++)
                v[r][c] = fmaxf(fmaf(v[r][c], s, t), 0.f);

#pragma unroll
        for (int j = 0; j < 2; j++) {
            const int pc = pc0 + 2 * tcc + j;
            if (pr < PH && pc < PW) {
                float pv = fmaxf(fmaxf(v[0][2 * j], v[0][2 * j + 1]),
                                 fmaxf(v[1][2 * j], v[1][2 * j + 1]));
                out[(((size_t)img * PH + pr) * PW + pc) * 64 + och] = pv;
            }
        }
    }
}

// ---------------- x @ Wk + bias (640 x 1600 @ 1600 x 128) ----------------
__global__ void xwk_gemm(const float* __restrict__ emb,
                         const float* __restrict__ Wk,
                         const float* __restrict__ bias,
                         float* __restrict__ outp)
{
    int idx = blockIdx.x * blockDim.x + threadIdx.x;
    if (idx >= NIMG * GATES) return;
    int u = idx & (GATES - 1);
    int n = idx >> 7;
    const float* e = emb + (size_t)n * DEMB;
    float acc = __ldg(bias + u);
#pragma unroll 4
    for (int k = 0; k < DEMB; k += 4) {
        float4 ev = *reinterpret_cast<const float4*>(e + k);
        acc = fmaf(ev.x, __ldg(Wk + (size_t)(k + 0) * GATES + u), acc);
        acc = fmaf(ev.y, __ldg(Wk + (size_t)(k + 1) * GATES + u), acc);
        acc = fmaf(ev.z, __ldg(Wk + (size_t)(k + 2) * GATES + u), acc);
        acc = fmaf(ev.w, __ldg(Wk + (size_t)(k + 3) * GATES + u), acc);
    }
    outp[idx] = acc;
}

// ---------------- LSTM chains over the BATCH axis ----------------
__device__ __forceinline__ float sigm(float x) { return 1.f / (1.f + expf(-x)); }

__global__ void lstm_chains(const float* __restrict__ xwkf,
                            const float* __restrict__ xwkb,
                            const float* __restrict__ Wrf,   // [32][128]
                            const float* __restrict__ Wrb,
                            float* __restrict__ sf,          // [25][16][32]
                            float* __restrict__ sb,
                            float* __restrict__ qf,          // [15][16][32]
                            float* __restrict__ qb)
{
    __shared__ float wr[HL * GATES];
    __shared__ float h[HL], c[HL], z[GATES];

    const int u     = threadIdx.x;       // 0..127
    const int chain = blockIdx.x;        // 0..39
    const int dir   = blockIdx.y;        // 0 fwd, 1 bwd

    const float* xwk = dir ? xwkb : xwkf;
    const float* Wr  = dir ? Wrb  : Wrf;
    float* outp = (chain < NS) ? (dir ? sb : sf) : (dir ? qb : qf);
    const int cpos = (chain < NS) ? chain : (chain - NS);

#pragma unroll
    for (int k = 0; k < HL; k++) wr[k * GATES + u] = Wr[k * GATES + u];
    if (u < HL) { h[u] = 0.f; c[u] = 0.f; }
    __syncthreads();

    for (int t = 0; t < NB; t++) {
        const int b = dir ? (NB - 1 - t) : t;
        const int row = (chain < NS) ? (b * NS + cpos) : (400 + b * NQ + cpos);

        float acc = __ldg(xwk + (size_t)row * GATES + u);
#pragma unroll
        for (int k = 0; k < HL; k++) acc = fmaf(h[k], wr[k * GATES + u], acc);
        z[u] = acc;
        __syncthreads();

        if (u < HL) {
            float zi = z[u];
            float zf = z[HL + u];
            float zg = z[2 * HL + u];
            float zo = z[3 * HL + u];
            float cc = sigm(zf) * c[u] + sigm(zi) * tanhf(zg);
            float hh = sigm(zo) * tanhf(cc);
            c[u] = cc; h[u] = hh;
            outp[(cpos * NB + b) * HL + u] = hh;
        }
        __syncthreads();
    }
}

// ---------------- attention readout + CE + accuracy ----------------
__global__ void readout(const float* __restrict__ sf,    // [25][16][32]
                        const float* __restrict__ sb,
                        const float* __restrict__ qf,    // [15][16][32]
                        const float* __restrict__ qb,
                        const int* __restrict__ ysup,    // [16][25]
                        const int* __restrict__ yqry,    // [16][15]
                        float* __restrict__ out)         // [17]
{
    __shared__ float ce_sm[NQ * NB];
    __shared__ float corr_sm[NQ * NB];
    const int t = threadIdx.x;   // 256

    if (t < NQ * NB) {
        const int q = t / NB, b = t % NB;
        float vf[HL], vb[HL];
#pragma unroll
        for (int j = 0; j < HL; j++) {
            vf[j] = qf[(q * NB + b) * HL + j];
            vb[j] = qb[(q * NB + b) * HL + j];
        }
        float scores[NS];
        float mx = -1e30f;
        for (int s = 0; s < NS; s++) {
            float dot = 0.f, nrm = 0.f;
#pragma unroll
            for (int j = 0; j < HL; j++) {
                float a = sf[(s * NB + b) * HL + j];
                dot = fmaf(vf[j], a, dot);
                nrm = fmaf(a, a, nrm);
            }
#pragma unroll
            for (int j = 0; j < HL; j++) {
                float a = sb[(s * NB + b) * HL + j];
                dot = fmaf(vb[j], a, dot);
                nrm = fmaf(a, a, nrm);
            }
            float sc = dot * rsqrtf(fmaxf(nrm, 1e-10f));
            scores[s] = sc;
            mx = fmaxf(mx, sc);
        }
        float sum = 0.f;
        for (int s = 0; s < NS; s++) { scores[s] = expf(scores[s] - mx); sum += scores[s]; }
        float inv = 1.f / sum;
        float preds[NWAY] = {0.f, 0.f, 0.f, 0.f, 0.f};
        for (int s = 0; s < NS; s++)
            preds[ysup[b * NS + s]] += scores[s] * inv;

        float psum = 0.f;
        for (int w = 0; w < NWAY; w++) psum += preds[w];
        const int yq = yqry[b * NQ + q];
        float pv = preds[yq] / psum;
        pv = fminf(fmaxf(pv, 1e-7f), 1.f - 1e-7f);
        ce_sm[t] = -logf(pv);

        int am = 0; float bv = preds[0];
        for (int w = 1; w < NWAY; w++) if (preds[w] > bv) { bv = preds[w]; am = w; }
        corr_sm[t] = (am == yq) ? 1.f : 0.f;
    }
    __syncthreads();
    if (t < NB) {
        float s = 0.f;
        for (int q = 0; q < NQ; q++) s += ce_sm[q * NB + t];
        out[t] = s / (float)NQ;
    }
    if (t == 16) {
        float s = 0.f;
        for (int i = 0; i < NQ * NB; i++) s += corr_sm[i];
        out[16] = s / (float)(NQ * NB);
    }
}

// ---------------- launch ----------------
extern "C" void kernel_launch(void* const* d_in, const int* in_sizes, int n_in,
                              void* d_out, int out_size)
{
    const float* xs = (const float*)d_in[0];
    const float* xq = (const float*)d_in[1];
    const int*   ys = (const int*)  d_in[2];
    const int*   yq = (const int*)  d_in[3];
    const float* w1 = (const float*)d_in[4];
    const float* w2 = (const float*)d_in[5];
    const float* w3 = (const float*)d_in[6];
    const float* w4 = (const float*)d_in[7];
    const float* cb = (const float*)d_in[8];
    const float* gm = (const float*)d_in[9];
    const float* bt = (const float*)d_in[10];
    const float* mn = (const float*)d_in[11];
    const float* vr = (const float*)d_in[12];
    const float* fk = (const float*)d_in[13];
    const float* fr = (const float*)d_in[14];
    const float* fb = (const float*)d_in[15];
    const float* bk = (const float*)d_in[16];
    const float* br = (const float*)d_in[17];
    const float* bb = (const float*)d_in[18];

    float *buf1, *buf2, *buf3, *emb, *xwkf, *xwkb, *sf, *sb, *qf, *qb;
    float4 *wdup;
    cudaGetSymbolAddress((void**)&buf1, g_buf1);
    cudaGetSymbolAddress((void**)&buf2, g_buf2);
    cudaGetSymbolAddress((void**)&buf3, g_buf3);
    cudaGetSymbolAddress((void**)&emb,  g_emb);
    cudaGetSymbolAddress((void**)&xwkf, g_xwkf);
    cudaGetSymbolAddress((void**)&xwkb, g_xwkb);
    cudaGetSymbolAddress((void**)&sf,   g_sf);
    cudaGetSymbolAddress((void**)&sb,   g_sb);
    cudaGetSymbolAddress((void**)&qf,   g_qf);
    cudaGetSymbolAddress((void**)&qb,   g_qb);
    cudaGetSymbolAddress((void**)&wdup, g_wdup);

    float4* wd1 = wdup;
    float4* wd2 = wdup + 864;
    float4* wd3 = wdup + 864 + 18432;
    float4* wd4 = wdup + 864 + 2 * 18432;

    // weight duplication (tiny)
    prep_w<<<(9 * 3  * 32 + 255) / 256, 256>>>(w1, wd1, 3);
    prep_w<<<(9 * 64 * 32 + 255) / 256, 256>>>(w2, wd2, 64);
    prep_w<<<(9 * 64 * 32 + 255) / 256, 256>>>(w3, wd3, 64);
    prep_w<<<(9 * 64 * 32 + 255) / 256, 256>>>(w4, wd4, 64);

    // layer 1: 84->42, 4x4 pooled block tile
    conv_bn_relu_pool<3, 84, 42, 4, 2, true><<<dim3(11, 11, 640), 256>>>(
        nullptr, xs, xq, (const ulonglong2*)wd1,
        cb + 0,   gm + 0,   bt + 0,   mn + 0,   vr + 0,   buf1);
    // layer 2: 42->21, 2x8 pooled block tile (dominant layer)
    conv_bn_relu_pool<64, 42, 21, 2, 4, false><<<dim3(3, 11, 640), 256>>>(
        buf1, nullptr, nullptr, (const ulonglong2*)wd2,
        cb + 64,  gm + 64,  bt + 64,  mn + 64,  vr + 64,  buf2);
    // layer 3: 21->10, 4x4 pooled block tile
    conv_bn_relu_pool<64, 21, 10, 4, 2, false><<<dim3(3, 3, 640), 256>>>(
        buf2, nullptr, nullptr, (const ulonglong2*)wd3,
        cb + 128, gm + 128, bt + 128, mn + 128, vr + 128, buf3);
    // layer 4: 10->5, 2x8 pooled block tile
    conv_bn_relu_pool<64, 10, 5, 2, 4, false><<<dim3(1, 3, 640), 256>>>(
        buf3, nullptr, nullptr, (const ulonglong2*)wd4,
        cb + 192, gm + 192, bt + 192, mn + 192, vr + 192, emb);

    // x @ Wk + bias for both LSTM directions
    xwk_gemm<<<(NIMG * GATES + 255) / 256, 256>>>(emb, fk, fb, xwkf);
    xwk_gemm<<<(NIMG * GATES + 255) / 256, 256>>>(emb, bk, bb, xwkb);

    // FCE: 40 position-chains x 2 directions, recurrence over the batch axis
    lstm_chains<<<dim3(40, 2), GATES>>>(xwkf, xwkb, fr, br, sf, sb, qf, qb);

    // attention + CE + acc
    readout<<<1, 256>>>(sf, sb, qf, qb, ys, yq, (float*)d_out);
}

// round 10
// speedup vs baseline: 1.7773x; 1.7773x over previous
#include <cuda_runtime.h>
#include <cuda_bf16.h>
#include <math.h>
#include <stdint.h>

// ---------------- problem constants ----------------
#define NB 16
#define NS 25
#define NQ 15
#define NWAY 5
#define NIMG 640            // 400 support + 240 query
#define HL 32
#define DEMB 1600           // 5*5*64
#define GATES 128           // 4*HL

// ---------------- scratch (device globals; no allocations allowed) ----------------
__device__ float g_buf1[640 * 42 * 42 * 64];   // after layer1 pool
__device__ float g_buf2[640 * 21 * 21 * 64];   // after layer2 pool
__device__ float g_buf3[640 * 10 * 10 * 64];   // after layer3 pool
__device__ float g_emb [640 * DEMB];           // embeddings (5*5*64)
__device__ float g_xwkf[640 * GATES];
__device__ float g_xwkb[640 * GATES];
__device__ float g_sf[NS * NB * HL];
__device__ float g_sb[NS * NB * HL];
__device__ float g_qf[NQ * NB * HL];
__device__ float g_qb[NQ * NB * HL];

// weight fragments for mma.sync m16n8k16: per layer, [tap][kstep][ntile][lane]
// uint4 = {bhi0, bhi1, blo0, blo1}  (9*4*8*32 = 9216 uint4 = 144KB per layer)
__device__ uint4 g_wfrag[3][9216];

// ---------------- bf16 split helpers ----------------
__device__ __forceinline__ uint32_t pack_hi2(float x0, float x1) {
    __nv_bfloat162 p = __halves2bfloat162(__float2bfloat16(x0), __float2bfloat16(x1));
    return *reinterpret_cast<uint32_t*>(&p);
}
__device__ __forceinline__ uint32_t pack_lo2(float x0, float x1) {
    __nv_bfloat16 h0 = __float2bfloat16(x0);
    __nv_bfloat16 h1 = __float2bfloat16(x1);
    __nv_bfloat162 p = __halves2bfloat162(__float2bfloat16(x0 - __bfloat162float(h0)),
                                          __float2bfloat16(x1 - __bfloat162float(h1)));
    return *reinterpret_cast<uint32_t*>(&p);
}

#define MMA_BF16(d, a, b0, b1) \
    asm volatile("mma.sync.aligned.m16n8k16.row.col.f32.bf16.bf16.f32 " \
        "{%0,%1,%2,%3}, {%4,%5,%6,%7}, {%8,%9}, {%0,%1,%2,%3};" \
        : "+f"((d)[0]), "+f"((d)[1]), "+f"((d)[2]), "+f"((d)[3]) \
        : "r"((a)[0]), "r"((a)[1]), "r"((a)[2]), "r"((a)[3]), "r"(b0), "r"(b1))

// ---------------- weight fragment prep ----------------
// src W[tap][cin=k][oc=n] (3*3*64*64 fp32). One thread -> one (tap,ks,nt,lane) uint4.
__global__ void prep_wfrag(const float* __restrict__ w, uint4* __restrict__ dst)
{
    int i = blockIdx.x * 256 + threadIdx.x;
    if (i >= 9216) return;
    int lane = i & 31;
    int nt   = (i >> 5) & 7;
    int ks   = (i >> 8) & 3;
    int tap  = i >> 10;
    int g = lane >> 2, l4 = lane & 3;
    int n  = nt * 8 + g;
    int k0 = ks * 16 + l4 * 2;
    float x00 = w[(tap * 64 + k0 + 0) * 64 + n];
    float x01 = w[(tap * 64 + k0 + 1) * 64 + n];
    float x10 = w[(tap * 64 + k0 + 8) * 64 + n];
    float x11 = w[(tap * 64 + k0 + 9) * 64 + n];
    uint4 o;
    o.x = pack_hi2(x00, x01);
    o.y = pack_hi2(x10, x11);
    o.z = pack_lo2(x00, x01);
    o.w = pack_lo2(x10, x11);
    dst[i] = o;
}

// ---------------- tensor conv (layers 2-4): conv3x3(SAME)+BN+ReLU+maxpool2x2 ----
// Persistent, 128 threads (4 warps). Tile = 16x8 conv pixels; warp w owns pixel
// rows 4w..4w+3 as two m16 tiles (2 rows x 8 cols each). bf16-split, fp32 accum.
#define SMW   0            // weight frags: 147456 B
#define SMAH  147456       // activation hi: 180 cells * 36 words * 4 = 25920 B
#define SMAL  173376       // activation lo: 25920 B
#define SMC   199296       // BN consts: 512 B
#define CONV_SMEM 199808

__global__ void __launch_bounds__(128, 1)
conv_tensor(const float* __restrict__ in,
            const uint4* __restrict__ wfrag,
            const float* __restrict__ cb, const float* __restrict__ gm,
            const float* __restrict__ bt, const float* __restrict__ mn,
            const float* __restrict__ vr,
            float* __restrict__ out,
            int H, int PH, int TR, int TC, int ntiles)
{
    extern __shared__ __align__(16) char smem[];
    const int tid = threadIdx.x;
    const int wrp = tid >> 5;
    const int lane = tid & 31;
    const int g = lane >> 2, l4 = lane & 3;

    // resident weight fragments -> SMEM
    {
        uint4* dw = (uint4*)(smem + SMW);
        for (int i = tid; i < 9216; i += 128) dw[i] = wfrag[i];
    }
    // BN fold constants
    if (tid < 64) {
        float s = gm[tid] * rsqrtf(vr[tid] + 1e-3f);
        float t = (cb[tid] - mn[tid]) * s + bt[tid];
        ((float*)(smem + SMC))[tid] = s;
        ((float*)(smem + SMC + 256))[tid] = t;
    }
    __syncthreads();

    uint32_t* sAh = (uint32_t*)(smem + SMAH);
    uint32_t* sAl = (uint32_t*)(smem + SMAL);
    const uint4* sW = (const uint4*)(smem + SMW);
    const float* sS = (const float*)(smem + SMC);
    const float* sT = (const float*)(smem + SMC + 256);
    const int tpi = TR * TC;

    for (int tile = blockIdx.x; tile < ntiles; tile += gridDim.x) {
        const int img  = tile / tpi;
        const int rem  = tile - img * tpi;
        const int r0   = (rem / TC) * 16;
        const int c0   = (rem % TC) * 8;
        const float* ibase = in + (size_t)img * H * H * 64;

        // ---- stage 18x10x64 window as bf16 hi/lo (pair-stride 36 words) ----
        for (int e = tid; e < 180 * 32; e += 128) {
            int pair = e & 31;
            int cell = e >> 5;               // wr*10 + wc
            int wr = cell / 10, wc = cell - 10 * wr;
            int gr = r0 - 1 + wr, gc = c0 - 1 + wc;
            float x0 = 0.f, x1 = 0.f;
            if (gr >= 0 && gr < H && gc >= 0 && gc < H) {
                float2 v = *(const float2*)(ibase + ((size_t)(gr * H + gc) << 6) + 2 * pair);
                x0 = v.x; x1 = v.y;
            }
            sAh[cell * 36 + pair] = pack_hi2(x0, x1);
            sAl[cell * 36 + pair] = pack_lo2(x0, x1);
        }
        __syncthreads();

        // ---- accumulate 9 taps x 4 ksteps over both m16 tiles ----
        float d[2][8][4];
#pragma unroll
        for (int mt = 0; mt < 2; mt++)
#pragma unroll
            for (int nt = 0; nt < 8; nt++)
#pragma unroll
                for (int j = 0; j < 4; j++) d[mt][nt][j] = 0.f;

        for (int tap = 0; tap < 9; tap++) {
            const int ky = tap / 3, kx = tap - 3 * (tap / 3);
#pragma unroll
            for (int ks = 0; ks < 4; ks++) {
                uint32_t ah[2][4], al[2][4];
#pragma unroll
                for (int mt = 0; mt < 2; mt++) {
                    const int rb = 4 * wrp + 2 * mt;           // pixel row base
                    const int cell0 = (rb + ky) * 10 + (g + kx);
                    const int cell1 = cell0 + 10;
                    const int p0 = ks * 8 + l4;
                    ah[mt][0] = sAh[cell0 * 36 + p0];
                    ah[mt][1] = sAh[cell1 * 36 + p0];
                    ah[mt][2] = sAh[cell0 * 36 + p0 + 4];
                    ah[mt][3] = sAh[cell1 * 36 + p0 + 4];
                    al[mt][0] = sAl[cell0 * 36 + p0];
                    al[mt][1] = sAl[cell1 * 36 + p0];
                    al[mt][2] = sAl[cell0 * 36 + p0 + 4];
                    al[mt][3] = sAl[cell1 * 36 + p0 + 4];
                }
                const uint4* wb = sW + ((tap * 4 + ks) * 8) * 32 + lane;
#pragma unroll
                for (int nt = 0; nt < 8; nt++) {
                    uint4 b = wb[nt * 32];
#pragma unroll
                    for (int mt = 0; mt < 2; mt++) {
                        MMA_BF16(d[mt][nt], ah[mt], b.x, b.y);   // hi*hi
                        MMA_BF16(d[mt][nt], al[mt], b.x, b.y);   // lo*hi
                        MMA_BF16(d[mt][nt], ah[mt], b.z, b.w);   // hi*lo
                    }
                }
            }
        }

        // ---- BN + ReLU + 2x2 maxpool + store ----
#pragma unroll
        for (int mt = 0; mt < 2; mt++) {
            const int pr = (r0 >> 1) + 2 * wrp + mt;
            const int pc = (c0 >> 1) + (g >> 1);
            const bool valid = ((g & 1) == 0) && pr < PH && pc < PH;
            float* obase = out + (((size_t)img * PH + pr) * PH + pc) * 64;
#pragma unroll
            for (int nt = 0; nt < 8; nt++) {
                const int oc = nt * 8 + l4 * 2;
                float s0 = sS[oc], s1 = sS[oc + 1];
                float t0 = sT[oc], t1 = sT[oc + 1];
                float v0 = fmaxf(fmaf(d[mt][nt][0], s0, t0), 0.f);
                float v1 = fmaxf(fmaf(d[mt][nt][1], s1, t1), 0.f);
                float v2 = fmaxf(fmaf(d[mt][nt][2], s0, t0), 0.f);
                float v3 = fmaxf(fmaf(d[mt][nt][3], s1, t1), 0.f);
                float m0 = fmaxf(v0, v2);
                float m1 = fmaxf(v1, v3);
                m0 = fmaxf(m0, __shfl_xor_sync(0xffffffffu, m0, 4));
                m1 = fmaxf(m1, __shfl_xor_sync(0xffffffffu, m1, 4));
                if (valid) *(float2*)(obase + oc) = make_float2(m0, m1);
            }
        }
        __syncthreads();
    }
}

// ==================== layer 1: scalar fused conv (proven) ====================
template <int CIN, int H, int PH, int TTR, int TTC, bool FIRST>
__global__ void __launch_bounds__(256, 2)
conv_bn_relu_pool(const float* __restrict__ in,
                  const float* __restrict__ in_sup,
                  const float* __restrict__ in_qry,
                  const float* __restrict__ wt,
                  const float* __restrict__ cb,
                  const float* __restrict__ gm,
                  const float* __restrict__ bt,
                  const float* __restrict__ mn,
                  const float* __restrict__ vr,
                  float* __restrict__ out)
{
    constexpr int W    = H;
    constexpr int PW   = PH;
    constexpr int ROWS = 2 * TTR + 2;
    constexpr int COLS = 4 * TTC + 2;
    constexpr int STRIDE = (COLS + 3) & ~3;

    __shared__ __align__(16) float sIn[CIN * ROWS * STRIDE];

    const int tid = threadIdx.x;
    const int oc  = tid & 31;
    const int tt  = tid >> 5;
    const int a   = tt / TTC;
    const int tcc = tt % TTC;

    const int img = blockIdx.z;
    const int pr0 = blockIdx.y * TTR;
    const int pc0 = blockIdx.x * (2 * TTC);
    const int ir0 = 2 * pr0 - 1;
    const int ic0 = 2 * pc0 - 1;

    const float* base;
    if (FIRST) {
        base = (img < 400) ? (in_sup + (size_t)img * H * W * CIN)
                           : (in_qry + (size_t)(img - 400) * H * W * CIN);
    } else {
        base = in + (size_t)img * H * W * CIN;
    }

    constexpr int NELEM = CIN * ROWS * COLS;
    for (int e = tid; e < NELEM; e += 256) {
        int cin = e % CIN;
        int rc  = e / CIN;
        int r = rc / COLS, c = rc % COLS;
        int gr = ir0 + r, gc = ic0 + c;
        float v = 0.f;
        if (gr >= 0 && gr < H && gc >= 0 && gc < W)
            v = __ldg(base + ((size_t)gr * W + gc) * CIN + cin);
        sIn[(cin * ROWS + r) * STRIDE + c] = v;
    }
    __syncthreads();

    float acc[2][2][4];
#pragma unroll
    for (int h = 0; h < 2; h++)
#pragma unroll
        for (int r = 0; r < 2; r++)
#pragma unroll
            for (int c = 0; c < 4; c++) acc[h][r][c] = 0.f;

    const int sb = 2 * a * STRIDE + 4 * tcc;

    for (int cin = 0; cin < CIN; cin++) {
        float xr[4][6];
        const float* sp = &sIn[cin * ROWS * STRIDE + sb];
#pragma unroll
        for (int rr = 0; rr < 4; rr++) {
            float4 v4 = *reinterpret_cast<const float4*>(sp + rr * STRIDE);
            float2 v2 = *reinterpret_cast<const float2*>(sp + rr * STRIDE + 4);
            xr[rr][0] = v4.x; xr[rr][1] = v4.y; xr[rr][2] = v4.z; xr[rr][3] = v4.w;
            xr[rr][4] = v2.x; xr[rr][5] = v2.y;
        }
        const float* wp = wt + cin * 64 + oc;
#pragma unroll
        for (int ky = 0; ky < 3; ky++)
#pragma unroll
            for (int kx = 0; kx < 3; kx++) {
                const float* wq = wp + (ky * 3 + kx) * CIN * 64;
                float w0 = __ldg(wq);
                float w1 = __ldg(wq + 32);
#pragma unroll
                for (int r = 0; r < 2; r++)
#pragma unroll
                    for (int c = 0; c < 4; c++) {
                        float xv = xr[r + ky][c + kx];
                        acc[0][r][c] = fmaf(xv, w0, acc[0][r][c]);
                        acc[1][r][c] = fmaf(xv, w1, acc[1][r][c]);
                    }
            }
    }

    const int pr = pr0 + a;
#pragma unroll
    for (int h = 0; h < 2; h++) {
        const int och = oc + 32 * h;
        const float s = __ldg(gm + och) * rsqrtf(__ldg(vr + och) + 1e-3f);
        const float t = (__ldg(cb + och) - __ldg(mn + och)) * s + __ldg(bt + och);
        float v[2][4];
#pragma unroll
        for (int r = 0; r < 2; r++)
#pragma unroll
            for (int c = 0; c < 4; c++)
                v[r][c] = fmaxf(fmaf(acc[h][r][c], s, t), 0.f);
#pragma unroll
        for (int j = 0; j < 2; j++) {
            const int pc = pc0 + 2 * tcc + j;
            if (pr < PH && pc < PW) {
                float pv = fmaxf(fmaxf(v[0][2 * j], v[0][2 * j + 1]),
                                 fmaxf(v[1][2 * j], v[1][2 * j + 1]));
                out[(((size_t)img * PH + pr) * PW + pc) * 64 + och] = pv;
            }
        }
    }
}

// ---------------- x @ Wk + bias ----------------
__global__ void xwk_gemm(const float* __restrict__ emb,
                         const float* __restrict__ Wk,
                         const float* __restrict__ bias,
                         float* __restrict__ outp)
{
    int idx = blockIdx.x * blockDim.x + threadIdx.x;
    if (idx >= NIMG * GATES) return;
    int u = idx & (GATES - 1);
    int n = idx >> 7;
    const float* e = emb + (size_t)n * DEMB;
    float acc = __ldg(bias + u);
#pragma unroll 4
    for (int k = 0; k < DEMB; k += 4) {
        float4 ev = *reinterpret_cast<const float4*>(e + k);
        acc = fmaf(ev.x, __ldg(Wk + (size_t)(k + 0) * GATES + u), acc);
        acc = fmaf(ev.y, __ldg(Wk + (size_t)(k + 1) * GATES + u), acc);
        acc = fmaf(ev.z, __ldg(Wk + (size_t)(k + 2) * GATES + u), acc);
        acc = fmaf(ev.w, __ldg(Wk + (size_t)(k + 3) * GATES + u), acc);
    }
    outp[idx] = acc;
}

// ---------------- LSTM chains over the BATCH axis ----------------
__device__ __forceinline__ float sigm(float x) { return 1.f / (1.f + expf(-x)); }

__global__ void lstm_chains(const float* __restrict__ xwkf,
                            const float* __restrict__ xwkb,
                            const float* __restrict__ Wrf,
                            const float* __restrict__ Wrb,
                            float* __restrict__ sf, float* __restrict__ sb2,
                            float* __restrict__ qf, float* __restrict__ qb)
{
    __shared__ float wr[HL * GATES];
    __shared__ float h[HL], c[HL], z[GATES];

    const int u     = threadIdx.x;
    const int chain = blockIdx.x;
    const int dir   = blockIdx.y;

    const float* xwk = dir ? xwkb : xwkf;
    const float* Wr  = dir ? Wrb  : Wrf;
    float* outp = (chain < NS) ? (dir ? sb2 : sf) : (dir ? qb : qf);
    const int cpos = (chain < NS) ? chain : (chain - NS);

#pragma unroll
    for (int k = 0; k < HL; k++) wr[k * GATES + u] = Wr[k * GATES + u];
    if (u < HL) { h[u] = 0.f; c[u] = 0.f; }
    __syncthreads();

    for (int t = 0; t < NB; t++) {
        const int b = dir ? (NB - 1 - t) : t;
        const int row = (chain < NS) ? (b * NS + cpos) : (400 + b * NQ + cpos);
        float acc = __ldg(xwk + (size_t)row * GATES + u);
#pragma unroll
        for (int k = 0; k < HL; k++) acc = fmaf(h[k], wr[k * GATES + u], acc);
        z[u] = acc;
        __syncthreads();
        if (u < HL) {
            float zi = z[u], zf = z[HL + u], zg = z[2 * HL + u], zo = z[3 * HL + u];
            float cc = sigm(zf) * c[u] + sigm(zi) * tanhf(zg);
            float hh = sigm(zo) * tanhf(cc);
            c[u] = cc; h[u] = hh;
            outp[(cpos * NB + b) * HL + u] = hh;
        }
        __syncthreads();
    }
}

// ---------------- attention readout + CE + accuracy ----------------
__global__ void readout(const float* __restrict__ sf, const float* __restrict__ sb2,
                        const float* __restrict__ qf, const float* __restrict__ qb,
                        const int* __restrict__ ysup, const int* __restrict__ yqry,
                        float* __restrict__ out)
{
    __shared__ float ce_sm[NQ * NB];
    __shared__ float corr_sm[NQ * NB];
    const int t = threadIdx.x;

    if (t < NQ * NB) {
        const int q = t / NB, b = t % NB;
        float vf[HL], vb[HL];
#pragma unroll
        for (int j = 0; j < HL; j++) {
            vf[j] = qf[(q * NB + b) * HL + j];
            vb[j] = qb[(q * NB + b) * HL + j];
        }
        float scores[NS];
        float mx = -1e30f;
        for (int s = 0; s < NS; s++) {
            float dot = 0.f, nrm = 0.f;
#pragma unroll
            for (int j = 0; j < HL; j++) {
                float a = sf[(s * NB + b) * HL + j];
                dot = fmaf(vf[j], a, dot); nrm = fmaf(a, a, nrm);
            }
#pragma unroll
            for (int j = 0; j < HL; j++) {
                float a = sb2[(s * NB + b) * HL + j];
                dot = fmaf(vb[j], a, dot); nrm = fmaf(a, a, nrm);
            }
            float sc = dot * rsqrtf(fmaxf(nrm, 1e-10f));
            scores[s] = sc; mx = fmaxf(mx, sc);
        }
        float sum = 0.f;
        for (int s = 0; s < NS; s++) { scores[s] = expf(scores[s] - mx); sum += scores[s]; }
        float inv = 1.f / sum;
        float preds[NWAY] = {0.f, 0.f, 0.f, 0.f, 0.f};
        for (int s = 0; s < NS; s++) preds[ysup[b * NS + s]] += scores[s] * inv;

        float psum = 0.f;
        for (int w = 0; w < NWAY; w++) psum += preds[w];
        const int yq = yqry[b * NQ + q];
        float pv = preds[yq] / psum;
        pv = fminf(fmaxf(pv, 1e-7f), 1.f - 1e-7f);
        ce_sm[t] = -logf(pv);

        int am = 0; float bv = preds[0];
        for (int w = 1; w < NWAY; w++) if (preds[w] > bv) { bv = preds[w]; am = w; }
        corr_sm[t] = (am == yq) ? 1.f : 0.f;
    }
    __syncthreads();
    if (t < NB) {
        float s = 0.f;
        for (int q = 0; q < NQ; q++) s += ce_sm[q * NB + t];
        out[t] = s / (float)NQ;
    }
    if (t == 16) {
        float s = 0.f;
        for (int i = 0; i < NQ * NB; i++) s += corr_sm[i];
        out[16] = s / (float)(NQ * NB);
    }
}

// ---------------- launch ----------------
extern "C" void kernel_launch(void* const* d_in, const int* in_sizes, int n_in,
                              void* d_out, int out_size)
{
    const float* xs = (const float*)d_in[0];
    const float* xq = (const float*)d_in[1];
    const int*   ys = (const int*)  d_in[2];
    const int*   yq = (const int*)  d_in[3];
    const float* w1 = (const float*)d_in[4];
    const float* w2 = (const float*)d_in[5];
    const float* w3 = (const float*)d_in[6];
    const float* w4 = (const float*)d_in[7];
    const float* cb = (const float*)d_in[8];
    const float* gm = (const float*)d_in[9];
    const float* bt = (const float*)d_in[10];
    const float* mn = (const float*)d_in[11];
    const float* vr = (const float*)d_in[12];
    const float* fk = (const float*)d_in[13];
    const float* fr = (const float*)d_in[14];
    const float* fb = (const float*)d_in[15];
    const float* bk = (const float*)d_in[16];
    const float* br = (const float*)d_in[17];
    const float* bb = (const float*)d_in[18];

    float *buf1, *buf2, *buf3, *emb, *xwkf, *xwkb, *sf, *sb, *qf, *qb;
    uint4 *wfrag;
    cudaGetSymbolAddress((void**)&buf1, g_buf1);
    cudaGetSymbolAddress((void**)&buf2, g_buf2);
    cudaGetSymbolAddress((void**)&buf3, g_buf3);
    cudaGetSymbolAddress((void**)&emb,  g_emb);
    cudaGetSymbolAddress((void**)&xwkf, g_xwkf);
    cudaGetSymbolAddress((void**)&xwkb, g_xwkb);
    cudaGetSymbolAddress((void**)&sf,   g_sf);
    cudaGetSymbolAddress((void**)&sb,   g_sb);
    cudaGetSymbolAddress((void**)&qf,   g_qf);
    cudaGetSymbolAddress((void**)&qb,   g_qb);
    cudaGetSymbolAddress((void**)&wfrag, g_wfrag);

    cudaFuncSetAttribute(conv_tensor, cudaFuncAttributeMaxDynamicSharedMemorySize, CONV_SMEM);

    // weight fragment prep (tiny)
    prep_wfrag<<<36, 256>>>(w2, wfrag + 0 * 9216);
    prep_wfrag<<<36, 256>>>(w3, wfrag + 1 * 9216);
    prep_wfrag<<<36, 256>>>(w4, wfrag + 2 * 9216);

    // layer 1: scalar (CIN=3)
    conv_bn_relu_pool<3, 84, 42, 4, 2, true><<<dim3(11, 11, 640), 256>>>(
        nullptr, xs, xq, w1, cb + 0, gm + 0, bt + 0, mn + 0, vr + 0, buf1);

    // layers 2-4: mma.sync bf16 tensor path (persistent, grid=148)
    conv_tensor<<<148, 128, CONV_SMEM>>>(buf1, wfrag + 0 * 9216,
        cb + 64,  gm + 64,  bt + 64,  mn + 64,  vr + 64,  buf2, 42, 21, 3, 6, 640 * 18);
    conv_tensor<<<148, 128, CONV_SMEM>>>(buf2, wfrag + 1 * 9216,
        cb + 128, gm + 128, bt + 128, mn + 128, vr + 128, buf3, 21, 10, 2, 3, 640 * 6);
    conv_tensor<<<148, 128, CONV_SMEM>>>(buf3, wfrag + 2 * 9216,
        cb + 192, gm + 192, bt + 192, mn + 192, vr + 192, emb, 10, 5, 1, 2, 640 * 2);

    // FCE input projections
    xwk_gemm<<<(NIMG * GATES + 255) / 256, 256>>>(emb, fk, fb, xwkf);
    xwk_gemm<<<(NIMG * GATES + 255) / 256, 256>>>(emb, bk, bb, xwkb);

    // FCE chains (recurrence over the batch axis)
    lstm_chains<<<dim3(40, 2), GATES>>>(xwkf, xwkb, fr, br, sf, sb, qf, qb);

    // attention + CE + acc
    readout<<<1, 256>>>(sf, sb, qf, qb, ys, yq, (float*)d_out);
}